// round 6
// baseline (speedup 1.0000x reference)
#include <cuda_runtime.h>
#include <cuda_bf16.h>

// OneHotEncoder: per-row token histogram, tokens [256, 2048] i32 -> counts [256, 32000] f32,
// pad_idx=0 skipped. `lengths` input is dead in the reference.
//
// R3 strategy: eliminate the shared-memory histogram round-trip entirely.
// The 32.77 MB output must be written once no matter what, and the whole
// working set lives in L2 at steady state (no DRAM drain). So the minimal
// kernel is: one CTA per row -> zero the row with STG.128 (goes to L2),
// __syncthreads() (CTA-scope global ordering), then RED.ADD.F32 global
// atomics for each non-pad token. ~40 issued instructions per thread vs
// ~150 for the smem-histogram version. No smem -> 1024 thr/CTA, 2 CTAs/SM,
// all 256 CTAs in one wave.

#define VOCAB   32000
#define SEQ_T   2048
#define THREADS 1024

__global__ __launch_bounds__(THREADS, 2)
void onehot_red_kernel(const int* __restrict__ tokens,
                       float* __restrict__ out)
{
    const int row = blockIdx.x;
    const int tid = threadIdx.x;

    // --- zero this row's output: 32000 f32 = 8000 float4; 8000/1024 -> 8 iters ---
    float4* out4 = reinterpret_cast<float4*>(out + (size_t)row * VOCAB);
    const float4 z = make_float4(0.f, 0.f, 0.f, 0.f);
    #pragma unroll 8
    for (int i = tid; i < VOCAB / 4; i += THREADS) {
        out4[i] = z;
    }

    // CTA-scope barrier: all zero-stores in this block are ordered before
    // (and visible to) the atomics below. Rows are CTA-private, so no
    // cross-CTA ordering is needed.
    __syncthreads();

    // --- scatter: 2048 tokens / 1024 threads = one int2 (LDG.64) per thread ---
    float* row_out = out + (size_t)row * VOCAB;
    const int2 t = reinterpret_cast<const int2*>(tokens + (size_t)row * SEQ_T)[tid];
    if (t.x != 0) atomicAdd(row_out + t.x, 1.0f);   // RED.ADD.F32 (no return)
    if (t.y != 0) atomicAdd(row_out + t.y, 1.0f);
}

extern "C" void kernel_launch(void* const* d_in, const int* in_sizes, int n_in,
                              void* d_out, int out_size)
{
    const int* tokens = (const int*)d_in[0];   // [256, 2048] int32
    // d_in[1] = lengths, unused by the reference computation.
    float* out = (float*)d_out;                // [256, 32000] f32

    const int batch = in_sizes[0] / SEQ_T;     // 256

    onehot_red_kernel<<<batch, THREADS>>>(tokens, out);
}